// round 9
// baseline (speedup 1.0000x reference)
#include <cuda_runtime.h>
#include <cstdint>
#include <climits>

#define BB   8
#define NN   4096
#define CIN  64
#define CMLP 128
#define COUT 256
#define SS   1024
#define NSAMP 32

// ---------------- device scratch (no allocations allowed) ----------------
__device__ float d_g[BB * NN * COUT];        // per-point post-MLP features (33.5 MB)
__device__ float d_Wcomb[CIN * COUT];        // W1 @ Wc
__device__ float d_bcomb[COUT];              // b1 @ Wc + bc
__device__ int   d_fpsidx[BB * SS];          // -1 sentinel, filled progressively by FPS
__device__ int   d_gidx[BB * SS * NSAMP];
__device__ int   d_counts[BB * NN];
__device__ float d_sum[COUT];
__device__ float d_sumsq[COUT];

// ---------------- packed fp32x2 helpers (bitwise-exact per-lane rn) ----------------
__device__ __forceinline__ unsigned long long f2_add(unsigned long long a, unsigned long long b) {
    unsigned long long r; asm("add.rn.f32x2 %0,%1,%2;" : "=l"(r) : "l"(a), "l"(b)); return r;
}
__device__ __forceinline__ unsigned long long f2_mul(unsigned long long a, unsigned long long b) {
    unsigned long long r; asm("mul.rn.f32x2 %0,%1,%2;" : "=l"(r) : "l"(a), "l"(b)); return r;
}
__device__ __forceinline__ unsigned long long f2_pack(float lo, float hi) {
    unsigned long long r; asm("mov.b64 %0,{%1,%2};" : "=l"(r) : "f"(lo), "f"(hi)); return r;
}
__device__ __forceinline__ void f2_unpack(float& lo, float& hi, unsigned long long v) {
    asm("mov.b64 {%0,%1},%2;" : "=f"(lo), "=f"(hi) : "l"(v));
}

// ---------------- K0: fold weights, init accumulators + sentinels ----------------
__global__ __launch_bounds__(256) void k0_prep(const float* __restrict__ W1,
                                               const float* __restrict__ b1,
                                               const float* __restrict__ Wc,
                                               const float* __restrict__ bc) {
    int blk = blockIdx.x, tid = threadIdx.x;
    if (blk < 64) {                       // Wcomb row blk
        const float* w1r = W1 + blk * CMLP;
        float acc = 0.f;
        for (int m = 0; m < CMLP; m++) acc += w1r[m] * Wc[m * COUT + tid];
        d_Wcomb[blk * COUT + tid] = acc;
    } else if (blk == 64) {               // bcomb
        float acc = bc[tid];
        for (int m = 0; m < CMLP; m++) acc += b1[m] * Wc[m * COUT + tid];
        d_bcomb[tid] = acc;
    } else if (blk < 193) {               // zero counts (128 blocks x 256)
        d_counts[(blk - 65) * 256 + tid] = 0;
    } else if (blk == 193) {              // zero stats
        d_sum[tid] = 0.f; d_sumsq[tid] = 0.f;
    } else {                              // fps sentinel (32 blocks x 256 = 8192)
        d_fpsidx[(blk - 194) * 256 + tid] = -1;
    }
}

// ---------------- K1: fused FPS (0..7) + GEMM (8..1031) + ball query (1032..1543) ----------------
__global__ __launch_bounds__(512) void k1_fused(const float* __restrict__ xyz,
                                                const float* __restrict__ points) {
    extern __shared__ float sm[];
    __shared__ unsigned long long s_key[3];
    __shared__ int sidx[16][NSAMP];
    int tid = threadIdx.x;

    if (blockIdx.x < BB) {
        // ============ exact FPS, one block per batch, 1 barrier/step ============
        float* sx = sm; float* sy = sm + NN; float* sz = sm + 2 * NN;
        volatile unsigned long long* vk = s_key;
        int b = blockIdx.x;
        const float* xb = xyz + b * NN * 3;
        for (int i = tid; i < NN; i += 512) {
            sx[i] = xb[3 * i]; sy[i] = xb[3 * i + 1]; sz[i] = xb[3 * i + 2];
        }
        if (tid == 0) { s_key[0] = 0ull; s_key[1] = 0ull; s_key[2] = 0ull; }
        __syncthreads();

        // thread t owns points t, t+512, ..., t+3584; pairs (2k,2k+1)
        unsigned long long p2x[4], p2y[4], p2z[4];
        float dmin[8];
        #pragma unroll
        for (int k = 0; k < 4; k++) {
            int i0 = tid + ((2 * k) << 9), i1 = tid + ((2 * k + 1) << 9);
            p2x[k] = f2_pack(sx[i0], sx[i1]);
            p2y[k] = f2_pack(sy[i0], sy[i1]);
            p2z[k] = f2_pack(sz[i0], sz[i1]);
        }
        #pragma unroll
        for (int j = 0; j < 8; j++) dmin[j] = 1e10f;

        int far = 0;
        int slot = 0;
        volatile int* fout = d_fpsidx + b * SS;

        for (int step = 0; step < SS; step++) {
            if (tid == 0) {
                fout[step] = far;                        // progressive publish (payload word)
                s_key[slot + 1 == 3 ? 0 : slot + 1] = 0ull;  // reset slot used at step+1
            }
            float cx = sx[far], cy = sy[far], cz = sz[far];
            // a + (-c) is bitwise identical to a - c (rn)
            unsigned long long ncx = f2_pack(-cx, -cx);
            unsigned long long ncy = f2_pack(-cy, -cy);
            unsigned long long ncz = f2_pack(-cz, -cz);

            float best = -1.0f;
            #pragma unroll
            for (int k = 0; k < 4; k++) {
                unsigned long long dx = f2_add(p2x[k], ncx);
                unsigned long long dy = f2_add(p2y[k], ncy);
                unsigned long long dz = f2_add(p2z[k], ncz);
                unsigned long long d2 = f2_add(f2_add(f2_mul(dx, dx), f2_mul(dy, dy)),
                                               f2_mul(dz, dz));
                float d0, d1; f2_unpack(d0, d1, d2);
                float m0 = fminf(dmin[2 * k],     d0); dmin[2 * k]     = m0;
                float m1 = fminf(dmin[2 * k + 1], d1); dmin[2 * k + 1] = m1;
                best = fmaxf(best, m0);
                best = fmaxf(best, m1);
            }

            unsigned fb = __float_as_uint(best);         // nonneg: uint order == float order
            unsigned wm = __reduce_max_sync(0xffffffffu, fb);
            if (fb == wm) {
                // only potential winners pay the argmax scan (first j -> lowest index)
                int bj = 0;
                #pragma unroll
                for (int j = 7; j >= 0; j--) if (dmin[j] == best) bj = j;
                unsigned long long key = ((unsigned long long)wm << 32)
                                       | (unsigned)~(unsigned)(tid + (bj << 9));
                // read-before-atomic: skip if a larger key is already posted
                // (monotone max -> stale-small read just issues a redundant atomic)
                if (key > vk[slot]) atomicMax(&s_key[slot], key);
            }
            __syncthreads();
            far = (int)(~(unsigned)vk[slot]);            // decode min-index of max-value
            slot = slot + 1 == 3 ? 0 : slot + 1;
        }
    } else if (blockIdx.x < BB + 1024) {
        // ============ GEMM: g = points @ Wcomb + bcomb (32 rows per block) ============
        float* sW = sm;                // 32 x 256 (phase-tiled over k)
        float* sP = sm + 32 * 256;     // 32 x 64
        int blk  = blockIdx.x - BB;
        int row0 = blk * 32;
        const float* pb = points + (size_t)row0 * CIN;
        for (int i = tid; i < 32 * CIN; i += 512) sP[i] = pb[i];

        int o    = tid & 255;
        int half = tid >> 8;           // 0/1: rows [0,16) or [16,32)
        float acc[16];
        float bo = d_bcomb[o];
        #pragma unroll
        for (int r = 0; r < 16; r++) acc[r] = bo;

        const float4* sP4 = (const float4*)sP;
        #pragma unroll
        for (int phase = 0; phase < 2; phase++) {
            if (phase) __syncthreads();
            for (int i = tid; i < 32 * 256; i += 512) sW[i] = d_Wcomb[phase * 8192 + i];
            __syncthreads();
            #pragma unroll
            for (int k4 = 0; k4 < 8; k4++) {
                float w0 = sW[(k4 * 4 + 0) * 256 + o];
                float w1 = sW[(k4 * 4 + 1) * 256 + o];
                float w2 = sW[(k4 * 4 + 2) * 256 + o];
                float w3 = sW[(k4 * 4 + 3) * 256 + o];
                #pragma unroll
                for (int r = 0; r < 16; r++) {
                    float4 p = sP4[(half * 16 + r) * 16 + phase * 8 + k4];
                    acc[r] = acc[r] + p.x * w0 + p.y * w1 + p.z * w2 + p.w * w3;
                }
            }
        }
        float* go = d_g + (size_t)row0 * COUT;
        #pragma unroll
        for (int r = 0; r < 16; r++) go[(half * 16 + r) * 256 + o] = acc[r];
    } else {
        // ============ ball query: 16 warps = 16 centroids per block, spin on fpsidx ============
        float* sx = sm; float* sy = sm + NN; float* sz = sm + 2 * NN;
        int idx = blockIdx.x - (BB + 1024);   // [0, 512)
        int b   = idx >> 6;                   // 64 blocks per batch
        int grp = (idx & 63) * 16;
        const float* xb = xyz + b * NN * 3;
        for (int i = tid; i < NN; i += 512) {
            sx[i] = xb[3 * i]; sy[i] = xb[3 * i + 1]; sz[i] = xb[3 * i + 2];
        }
        __syncthreads();

        int warp = tid >> 5, lane = tid & 31;
        int s = grp + warp;
        // spin until FPS publishes this centroid (payload word, no fence needed)
        volatile int* fp = d_fpsidx + b * SS + s;
        int fidx = *fp;
        while (fidx < 0) { __nanosleep(200); fidx = *fp; }

        float cx = sx[fidx], cy = sy[fidx], cz = sz[fidx];
        const float R2 = (float)(0.15 * 0.15);

        int K = 0;
        for (int c = 0; c < NN; c += 32) {
            int n = c + lane;
            float dx = __fsub_rn(sx[n], cx);
            float dy = __fsub_rn(sy[n], cy);
            float dz = __fsub_rn(sz[n], cz);
            float d  = __fadd_rn(__fadd_rn(__fmul_rn(dx, dx), __fmul_rn(dy, dy)),
                                 __fmul_rn(dz, dz));
            bool in = !(d > R2);                               // matches `sqr > r2` exclusion
            unsigned mask = __ballot_sync(0xffffffffu, in);
            int pos = K + __popc(mask & ((1u << lane) - 1u));
            if (in && pos < NSAMP) sidx[warp][pos] = n;
            K += __popc(mask);
            if (K >= NSAMP) break;                             // warp-uniform
        }
        __syncwarp();
        int Kc = K < NSAMP ? K : NSAMP;                        // centroid always in-radius -> K>=1
        int first = sidx[warp][0];
        if (lane >= Kc) sidx[warp][lane] = first;              // pad with first index
        __syncwarp();
        int gi = sidx[warp][lane];
        d_gidx[(b * SS + s) * NSAMP + lane] = gi;
        atomicAdd(&d_counts[b * NN + gi], 1);                  // duplicates counted (matches gather)
    }
}

// ---------------- K3: count-weighted per-channel sums (2048 blocks x 16 rows) ----------------
__global__ __launch_bounds__(256) void k3_stats() {
    int o  = threadIdx.x;
    int r0 = blockIdx.x * 16;
    float s = 0.f, q = 0.f;
    #pragma unroll 4
    for (int r = 0; r < 16; r++) {
        int row = r0 + r;
        int c = d_counts[row];
        if (c) {
            float fc = (float)c;
            float v  = d_g[(size_t)row * COUT + o];
            s += fc * v;
            q += fc * v * v;
        }
    }
    atomicAdd(&d_sum[o], s);
    atomicAdd(&d_sumsq[o], q);
}

// ---------------- K5: BN finalize (per-block, deterministic) + gather + affine + relu + max ----------------
__global__ __launch_bounds__(256) void k5_out(const float* __restrict__ gamma,
                                              const float* __restrict__ beta,
                                              float* __restrict__ out) {
    __shared__ int si[NSAMP];
    int bs  = blockIdx.x;                  // b*1024 + s
    int tid = threadIdx.x;
    if (tid < NSAMP) si[tid] = d_gidx[bs * NSAMP + tid];
    __syncthreads();
    // fold BN finalize here (identical arithmetic in every block -> deterministic)
    const float invn = 1.0f / (float)(BB * SS * NSAMP);    // 1/262144
    float mean = d_sum[tid] * invn;
    float var  = d_sumsq[tid] * invn - mean * mean;
    float sc   = gamma[tid] / sqrtf(var + 1e-5f);
    float sh   = beta[tid] - mean * sc;

    int b = bs >> 10;
    const float* gb = d_g + (size_t)b * NN * COUT;
    float m = -3.4e38f;
    #pragma unroll
    for (int j = 0; j < NSAMP; j++) {
        float v = gb[(size_t)si[j] * COUT + tid];
        m = fmaxf(m, v * sc + sh);
    }
    out[(size_t)bs * COUT + tid] = fmaxf(m, 0.0f);         // relu commutes with max
}

// ---------------- launcher ----------------
extern "C" void kernel_launch(void* const* d_in, const int* in_sizes, int n_in,
                              void* d_out, int out_size) {
    const float* xyz    = (const float*)d_in[0];   // (8,4096,3)
    // d_in[1] = t (unused by reference)
    const float* points = (const float*)d_in[2];   // (8,4096,64)
    const float* W1     = (const float*)d_in[3];   // (64,128)
    const float* b1     = (const float*)d_in[4];   // (128)
    const float* Wc     = (const float*)d_in[5];   // (128,256)
    const float* bc     = (const float*)d_in[6];   // (256)
    const float* gamma  = (const float*)d_in[7];   // (256)
    const float* beta   = (const float*)d_in[8];   // (256)
    float* out = (float*)d_out;                    // (8,1024,256)

    const int SMEM_XYZ = 3 * NN * sizeof(float);   // 49152 bytes dynamic

    // One-time opt-in (runs on the correctness call, before graph capture).
    static const bool attrs_ok = [](){
        cudaFuncSetAttribute(k1_fused,
                             cudaFuncAttributeMaxDynamicSharedMemorySize, 56 * 1024);
        return true;
    }();
    (void)attrs_ok;

    k0_prep<<<226, 256>>>(W1, b1, Wc, bc);
    k1_fused<<<BB + 1024 + 512, 512, SMEM_XYZ>>>(xyz, points);
    k3_stats<<<2048, 256>>>();
    k5_out<<<BB * SS, 256>>>(gamma, beta, out);
}

// round 11
// speedup vs baseline: 1.1685x; 1.1685x over previous
#include <cuda_runtime.h>
#include <cstdint>
#include <climits>

#define BB   8
#define NN   4096
#define CIN  64
#define CMLP 128
#define COUT 256
#define SS   1024
#define NSAMP 32

// ---------------- device scratch (no allocations allowed) ----------------
__device__ float d_g[BB * NN * COUT];        // per-point post-MLP features (33.5 MB)
__device__ float d_Wcomb[CIN * COUT];        // W1 @ Wc
__device__ float d_bcomb[COUT];              // b1 @ Wc + bc
__device__ int   d_fpsidx[BB * SS];          // -1 sentinel, filled progressively by FPS
__device__ int   d_gidx[BB * SS * NSAMP];
__device__ int   d_counts[BB * NN];
__device__ float d_sum[COUT];
__device__ float d_sumsq[COUT];

// ---------------- packed fp32x2 helpers (bitwise-exact per-lane rn) ----------------
__device__ __forceinline__ unsigned long long f2_add(unsigned long long a, unsigned long long b) {
    unsigned long long r; asm("add.rn.f32x2 %0,%1,%2;" : "=l"(r) : "l"(a), "l"(b)); return r;
}
__device__ __forceinline__ unsigned long long f2_mul(unsigned long long a, unsigned long long b) {
    unsigned long long r; asm("mul.rn.f32x2 %0,%1,%2;" : "=l"(r) : "l"(a), "l"(b)); return r;
}
__device__ __forceinline__ unsigned long long f2_pack(float lo, float hi) {
    unsigned long long r; asm("mov.b64 %0,{%1,%2};" : "=l"(r) : "f"(lo), "f"(hi)); return r;
}
__device__ __forceinline__ void f2_unpack(float& lo, float& hi, unsigned long long v) {
    asm("mov.b64 {%0,%1},%2;" : "=f"(lo), "=f"(hi) : "l"(v));
}

// ---------------- K0: fold weights, init accumulators + sentinels ----------------
__global__ __launch_bounds__(256) void k0_prep(const float* __restrict__ W1,
                                               const float* __restrict__ b1,
                                               const float* __restrict__ Wc,
                                               const float* __restrict__ bc) {
    int blk = blockIdx.x, tid = threadIdx.x;
    if (blk < 64) {                       // Wcomb row blk
        const float* w1r = W1 + blk * CMLP;
        float acc = 0.f;
        for (int m = 0; m < CMLP; m++) acc += w1r[m] * Wc[m * COUT + tid];
        d_Wcomb[blk * COUT + tid] = acc;
    } else if (blk == 64) {               // bcomb
        float acc = bc[tid];
        for (int m = 0; m < CMLP; m++) acc += b1[m] * Wc[m * COUT + tid];
        d_bcomb[tid] = acc;
    } else if (blk < 193) {               // zero counts (128 blocks x 256)
        d_counts[(blk - 65) * 256 + tid] = 0;
    } else if (blk == 193) {              // zero stats
        d_sum[tid] = 0.f; d_sumsq[tid] = 0.f;
    } else {                              // fps sentinel (32 blocks x 256 = 8192)
        d_fpsidx[(blk - 194) * 256 + tid] = -1;
    }
}

// ---------------- K1: fused FPS (0..7) + GEMM (8..1031) + ball query (1032..1543) ----------------
__global__ __launch_bounds__(512) void k1_fused(const float* __restrict__ xyz,
                                                const float* __restrict__ points) {
    extern __shared__ float sm[];
    __shared__ unsigned long long s_wkeys[2][8];   // [parity][warp] -- FPS reduction keys
    __shared__ int sidx[16][NSAMP];
    int tid = threadIdx.x;

    if (blockIdx.x < BB) {
        // ============ exact FPS: 8 warps, 16 pts/thread, STS-key reduction (no atomics) ============
        float* sx = sm; float* sy = sm + NN; float* sz = sm + 2 * NN;
        int b = blockIdx.x;
        const float* xb = xyz + b * NN * 3;
        for (int i = tid; i < NN; i += 512) {
            sx[i] = xb[3 * i]; sy[i] = xb[3 * i + 1]; sz[i] = xb[3 * i + 2];
        }
        __syncthreads();                         // full block: xyz staged
        if (tid >= 256) return;                  // warps 8..15 retire; 8 warps continue

        // thread t owns points t, t+256, ..., t+3840 (ascending j -> ascending idx)
        unsigned long long p2x[8], p2y[8], p2z[8];
        float dmin[16];
        #pragma unroll
        for (int k = 0; k < 8; k++) {
            int i0 = tid + ((2 * k) << 8), i1 = tid + ((2 * k + 1) << 8);
            p2x[k] = f2_pack(sx[i0], sx[i1]);
            p2y[k] = f2_pack(sy[i0], sy[i1]);
            p2z[k] = f2_pack(sz[i0], sz[i1]);
        }
        #pragma unroll
        for (int j = 0; j < 16; j++) dmin[j] = 1e10f;

        int far = 0;
        int lane = tid & 31, warp = tid >> 5;
        volatile int* fout = d_fpsidx + b * SS;

        for (int step = 0; step < SS; step++) {
            if (tid == 0) fout[step] = far;      // progressive publish (payload word)
            float cx = sx[far], cy = sy[far], cz = sz[far];
            // a + (-c) is bitwise identical to a - c (rn)
            unsigned long long ncx = f2_pack(-cx, -cx);
            unsigned long long ncy = f2_pack(-cy, -cy);
            unsigned long long ncz = f2_pack(-cz, -cz);

            float best = -1.0f;
            #pragma unroll
            for (int k = 0; k < 8; k++) {
                unsigned long long dx = f2_add(p2x[k], ncx);
                unsigned long long dy = f2_add(p2y[k], ncy);
                unsigned long long dz = f2_add(p2z[k], ncz);
                unsigned long long d2 = f2_add(f2_add(f2_mul(dx, dx), f2_mul(dy, dy)),
                                               f2_mul(dz, dz));
                float d0, d1; f2_unpack(d0, d1, d2);
                float m0 = fminf(dmin[2 * k],     d0); dmin[2 * k]     = m0;
                float m1 = fminf(dmin[2 * k + 1], d1); dmin[2 * k + 1] = m1;
                best = fmaxf(best, m0);
                best = fmaxf(best, m1);
            }

            unsigned fb = __float_as_uint(best);       // nonneg: uint order == float order
            unsigned wm = __reduce_max_sync(0xffffffffu, fb);
            int cand = 0x7fffffff;
            if (fb == wm) {
                int bj = 0;                            // first j == lowest in-thread index
                #pragma unroll
                for (int j = 15; j >= 0; j--) if (dmin[j] == best) bj = j;
                cand = tid + (bj << 8);
            }
            int wi = __reduce_min_sync(0xffffffffu, cand);   // lowest idx among warp maxima
            int par = step & 1;
            if (lane == 0)
                s_wkeys[par][warp] = ((unsigned long long)wm << 32) | (unsigned)~wi;

            asm volatile("bar.sync 1, 256;" ::: "memory");   // 8-warp barrier (drains STS)

            // fold 8 keys: max value, then min index (via ~idx) -- identical in all threads
            unsigned long long kmax = s_wkeys[par][0];
            #pragma unroll
            for (int w = 1; w < 8; w++) {
                unsigned long long kv = s_wkeys[par][w];
                kmax = kv > kmax ? kv : kmax;
            }
            far = (int)(~(unsigned)kmax);
        }
    } else if (blockIdx.x < BB + 1024) {
        // ============ GEMM: g = points @ Wcomb + bcomb (32 rows per block) ============
        float* sW = sm;                // 32 x 256 (phase-tiled over k)
        float* sP = sm + 32 * 256;     // 32 x 64
        int blk  = blockIdx.x - BB;
        int row0 = blk * 32;
        const float* pb = points + (size_t)row0 * CIN;
        for (int i = tid; i < 32 * CIN; i += 512) sP[i] = pb[i];

        int o    = tid & 255;
        int half = tid >> 8;           // 0/1: rows [0,16) or [16,32)
        float acc[16];
        float bo = d_bcomb[o];
        #pragma unroll
        for (int r = 0; r < 16; r++) acc[r] = bo;

        const float4* sP4 = (const float4*)sP;
        #pragma unroll
        for (int phase = 0; phase < 2; phase++) {
            if (phase) __syncthreads();
            for (int i = tid; i < 32 * 256; i += 512) sW[i] = d_Wcomb[phase * 8192 + i];
            __syncthreads();
            #pragma unroll
            for (int k4 = 0; k4 < 8; k4++) {
                float w0 = sW[(k4 * 4 + 0) * 256 + o];
                float w1 = sW[(k4 * 4 + 1) * 256 + o];
                float w2 = sW[(k4 * 4 + 2) * 256 + o];
                float w3 = sW[(k4 * 4 + 3) * 256 + o];
                #pragma unroll
                for (int r = 0; r < 16; r++) {
                    float4 p = sP4[(half * 16 + r) * 16 + phase * 8 + k4];
                    acc[r] = acc[r] + p.x * w0 + p.y * w1 + p.z * w2 + p.w * w3;
                }
            }
        }
        float* go = d_g + (size_t)row0 * COUT;
        #pragma unroll
        for (int r = 0; r < 16; r++) go[(half * 16 + r) * 256 + o] = acc[r];
    } else {
        // ============ ball query: 16 warps = 16 centroids per block, spin on fpsidx ============
        float* sx = sm; float* sy = sm + NN; float* sz = sm + 2 * NN;
        int idx = blockIdx.x - (BB + 1024);   // [0, 512)
        int b   = idx >> 6;                   // 64 blocks per batch
        int grp = (idx & 63) * 16;
        const float* xb = xyz + b * NN * 3;
        for (int i = tid; i < NN; i += 512) {
            sx[i] = xb[3 * i]; sy[i] = xb[3 * i + 1]; sz[i] = xb[3 * i + 2];
        }
        __syncthreads();

        int warp = tid >> 5, lane = tid & 31;
        int s = grp + warp;
        // spin until FPS publishes this centroid (payload word, no fence needed)
        volatile int* fp = d_fpsidx + b * SS + s;
        int fidx = *fp;
        while (fidx < 0) { __nanosleep(200); fidx = *fp; }

        float cx = sx[fidx], cy = sy[fidx], cz = sz[fidx];
        const float R2 = (float)(0.15 * 0.15);

        int K = 0;
        for (int c = 0; c < NN; c += 32) {
            int n = c + lane;
            float dx = __fsub_rn(sx[n], cx);
            float dy = __fsub_rn(sy[n], cy);
            float dz = __fsub_rn(sz[n], cz);
            float d  = __fadd_rn(__fadd_rn(__fmul_rn(dx, dx), __fmul_rn(dy, dy)),
                                 __fmul_rn(dz, dz));
            bool in = !(d > R2);                               // matches `sqr > r2` exclusion
            unsigned mask = __ballot_sync(0xffffffffu, in);
            int pos = K + __popc(mask & ((1u << lane) - 1u));
            if (in && pos < NSAMP) sidx[warp][pos] = n;
            K += __popc(mask);
            if (K >= NSAMP) break;                             // warp-uniform
        }
        __syncwarp();
        int Kc = K < NSAMP ? K : NSAMP;                        // centroid always in-radius -> K>=1
        int first = sidx[warp][0];
        if (lane >= Kc) sidx[warp][lane] = first;              // pad with first index
        __syncwarp();
        int gi = sidx[warp][lane];
        d_gidx[(b * SS + s) * NSAMP + lane] = gi;
        atomicAdd(&d_counts[b * NN + gi], 1);                  // duplicates counted (matches gather)
    }
}

// ---------------- K3: count-weighted per-channel sums (2048 blocks x 16 rows) ----------------
__global__ __launch_bounds__(256) void k3_stats() {
    int o  = threadIdx.x;
    int r0 = blockIdx.x * 16;
    float s = 0.f, q = 0.f;
    #pragma unroll 4
    for (int r = 0; r < 16; r++) {
        int row = r0 + r;
        int c = d_counts[row];
        if (c) {
            float fc = (float)c;
            float v  = d_g[(size_t)row * COUT + o];
            s += fc * v;
            q += fc * v * v;
        }
    }
    atomicAdd(&d_sum[o], s);
    atomicAdd(&d_sumsq[o], q);
}

// ---------------- K5: BN finalize (per-block, deterministic) + gather + affine + relu + max ----------------
__global__ __launch_bounds__(256) void k5_out(const float* __restrict__ gamma,
                                              const float* __restrict__ beta,
                                              float* __restrict__ out) {
    __shared__ int si[NSAMP];
    int bs  = blockIdx.x;                  // b*1024 + s
    int tid = threadIdx.x;
    if (tid < NSAMP) si[tid] = d_gidx[bs * NSAMP + tid];
    __syncthreads();
    // fold BN finalize here (identical arithmetic in every block -> deterministic)
    const float invn = 1.0f / (float)(BB * SS * NSAMP);    // 1/262144
    float mean = d_sum[tid] * invn;
    float var  = d_sumsq[tid] * invn - mean * mean;
    float sc   = gamma[tid] / sqrtf(var + 1e-5f);
    float sh   = beta[tid] - mean * sc;

    int b = bs >> 10;
    const float* gb = d_g + (size_t)b * NN * COUT;
    float m = -3.4e38f;
    #pragma unroll
    for (int j = 0; j < NSAMP; j++) {
        float v = gb[(size_t)si[j] * COUT + tid];
        m = fmaxf(m, v * sc + sh);
    }
    out[(size_t)bs * COUT + tid] = fmaxf(m, 0.0f);         // relu commutes with max
}

// ---------------- launcher ----------------
extern "C" void kernel_launch(void* const* d_in, const int* in_sizes, int n_in,
                              void* d_out, int out_size) {
    const float* xyz    = (const float*)d_in[0];   // (8,4096,3)
    // d_in[1] = t (unused by reference)
    const float* points = (const float*)d_in[2];   // (8,4096,64)
    const float* W1     = (const float*)d_in[3];   // (64,128)
    const float* b1     = (const float*)d_in[4];   // (128)
    const float* Wc     = (const float*)d_in[5];   // (128,256)
    const float* bc     = (const float*)d_in[6];   // (256)
    const float* gamma  = (const float*)d_in[7];   // (256)
    const float* beta   = (const float*)d_in[8];   // (256)
    float* out = (float*)d_out;                    // (8,1024,256)

    const int SMEM_XYZ = 3 * NN * sizeof(float);   // 49152 bytes dynamic

    // One-time opt-in (runs on the correctness call, before graph capture).
    static const bool attrs_ok = [](){
        cudaFuncSetAttribute(k1_fused,
                             cudaFuncAttributeMaxDynamicSharedMemorySize, 56 * 1024);
        return true;
    }();
    (void)attrs_ok;

    k0_prep<<<226, 256>>>(W1, b1, Wc, bc);
    k1_fused<<<BB + 1024 + 512, 512, SMEM_XYZ>>>(xyz, points);
    k3_stats<<<2048, 256>>>();
    k5_out<<<BB * SS, 256>>>(gamma, beta, out);
}